// round 5
// baseline (speedup 1.0000x reference)
#include <cuda_runtime.h>
#include <math_constants.h>

#define B_      64
#define T_      2048
#define RNN_    1024
#define EMB_    512
#define ATT_    128
#define NF_     32
#define KS_     31
#define PAD_    15
#define TILE_   128

// scratch (no allocs allowed)
__device__ float g_pq[B_ * ATT_];       // processed query [B,128]
__device__ float g_energy[B_ * T_];     // pre-softmax energies [B,T]

// ---------------------------------------------------------------------------
// K1: g_pq[b,a] = sum_r query[b,r] * W_query[a,r]
// 64 blocks x 256 threads; 2 threads per 'a' (split-K over 512 each)
// ---------------------------------------------------------------------------
__global__ __launch_bounds__(256) void k_query(const float* __restrict__ q,
                                               const float* __restrict__ Wq) {
    int b = blockIdx.x;
    int a = threadIdx.x & 127;
    int half = threadIdx.x >> 7;
    __shared__ float s_q[RNN_];
    __shared__ float s_p[ATT_];
    for (int i = threadIdx.x; i < RNN_; i += 256) s_q[i] = q[b * RNN_ + i];
    __syncthreads();
    const float4* w4 = reinterpret_cast<const float4*>(Wq + (size_t)a * RNN_) + half * 128;
    const float4* q4 = reinterpret_cast<const float4*>(s_q) + half * 128;
    float acc = 0.f;
#pragma unroll 8
    for (int j = 0; j < 128; j++) {
        float4 w = w4[j];
        float4 x = q4[j];
        acc += w.x * x.x + w.y * x.y + w.z * x.z + w.w * x.w;
    }
    if (half) s_p[a] = acc;
    __syncthreads();
    if (!half) g_pq[b * ATT_ + a] = acc + s_p[a];
}

// ---------------------------------------------------------------------------
// K2: energies. grid (T/TILE, B), 128 threads (thread = attention dim a).
// Fuses: conv(attn_weights_cat) -> loc; loc @ W_loc; + pm + pq; tanh; dot v;
// mask -> -inf; writes g_energy.
// ---------------------------------------------------------------------------
__global__ __launch_bounds__(128) void k_energy(const float* __restrict__ pm,
                                                const float* __restrict__ cat,
                                                const int* __restrict__ mask,
                                                const float* __restrict__ cw,
                                                const float* __restrict__ Wl,
                                                const float* __restrict__ vw) {
    const int b = blockIdx.y;
    const int t0 = blockIdx.x * TILE_;
    const int tid = threadIdx.x;

    __shared__ __align__(16) float s_cat[2][TILE_ + 32];    // window + zero pad
    __shared__ __align__(16) float s_cw[2][NF_][32];        // [c][f][k], k padded to 32
    __shared__ float4 s_loc[8][TILE_];                      // [f-group][t] -> f=4j..4j+3
    __shared__ float s_part[4][TILE_];                      // per-warp partial energies

    // load input window (with boundary + tail zero padding)
#pragma unroll
    for (int c = 0; c < 2; c++) {
        for (int i = tid; i < TILE_ + 32; i += 128) {
            int g = t0 - PAD_ + i;
            float v = 0.f;
            if (i < TILE_ + 2 * PAD_ && g >= 0 && g < T_)
                v = cat[((size_t)(b * 2 + c)) * T_ + g];
            s_cat[c][i] = v;
        }
    }
    // load conv weights transposed [c][f][k], pad k=31 with 0
    for (int i = tid; i < 2 * NF_ * 32; i += 128) {
        int c = i >> 10;
        int f = (i >> 5) & 31;
        int k = i & 31;
        s_cw[c][f][k] = (k < KS_) ? cw[(f * 2 + c) * KS_ + k] : 0.f;
    }
    __syncthreads();

    // ---- conv phase: thread = local time index t=tid, 32 filters ----
    {
        float xr0[32], xr1[32];
#pragma unroll
        for (int i = 0; i < 32; i++) {
            xr0[i] = s_cat[0][tid + i];
            xr1[i] = s_cat[1][tid + i];
        }
#pragma unroll
        for (int j = 0; j < 8; j++) {
            float a0 = 0.f, a1 = 0.f, a2 = 0.f, a3 = 0.f;
#pragma unroll
            for (int kk = 0; kk < 8; kk++) {
                float x0 = xr0[4 * kk + 0], x1 = xr0[4 * kk + 1];
                float x2 = xr0[4 * kk + 2], x3 = xr0[4 * kk + 3];
                float4 w0 = *reinterpret_cast<const float4*>(&s_cw[0][4 * j + 0][4 * kk]);
                float4 w1 = *reinterpret_cast<const float4*>(&s_cw[0][4 * j + 1][4 * kk]);
                float4 w2 = *reinterpret_cast<const float4*>(&s_cw[0][4 * j + 2][4 * kk]);
                float4 w3 = *reinterpret_cast<const float4*>(&s_cw[0][4 * j + 3][4 * kk]);
                a0 += w0.x * x0 + w0.y * x1 + w0.z * x2 + w0.w * x3;
                a1 += w1.x * x0 + w1.y * x1 + w1.z * x2 + w1.w * x3;
                a2 += w2.x * x0 + w2.y * x1 + w2.z * x2 + w2.w * x3;
                a3 += w3.x * x0 + w3.y * x1 + w3.z * x2 + w3.w * x3;
                float y0 = xr1[4 * kk + 0], y1 = xr1[4 * kk + 1];
                float y2 = xr1[4 * kk + 2], y3 = xr1[4 * kk + 3];
                float4 u0 = *reinterpret_cast<const float4*>(&s_cw[1][4 * j + 0][4 * kk]);
                float4 u1 = *reinterpret_cast<const float4*>(&s_cw[1][4 * j + 1][4 * kk]);
                float4 u2 = *reinterpret_cast<const float4*>(&s_cw[1][4 * j + 2][4 * kk]);
                float4 u3 = *reinterpret_cast<const float4*>(&s_cw[1][4 * j + 3][4 * kk]);
                a0 += u0.x * y0 + u0.y * y1 + u0.z * y2 + u0.w * y3;
                a1 += u1.x * y0 + u1.y * y1 + u1.z * y2 + u1.w * y3;
                a2 += u2.x * y0 + u2.y * y1 + u2.z * y2 + u2.w * y3;
                a3 += u3.x * y0 + u3.y * y1 + u3.z * y2 + u3.w * y3;
            }
            s_loc[j][tid] = make_float4(a0, a1, a2, a3);
        }
    }
    __syncthreads();

    // ---- energies phase: thread = a, loop over t ----
    float4 wl4[8];
    {
        const float4* wlg = reinterpret_cast<const float4*>(Wl + tid * NF_);
#pragma unroll
        for (int j = 0; j < 8; j++) wl4[j] = wlg[j];
    }
    const float va = vw[tid];
    const float pqa = g_pq[b * ATT_ + tid];
    const int w = tid >> 5, lane = tid & 31;
    const float* pmb = pm + ((size_t)(b * T_ + t0)) * ATT_ + tid;

#pragma unroll 2
    for (int t = 0; t < TILE_; t++) {
        float acc = pqa + pmb[(size_t)t * ATT_];
#pragma unroll
        for (int j = 0; j < 8; j++) {
            float4 l = s_loc[j][t];
            float4 wv = wl4[j];
            acc += l.x * wv.x + l.y * wv.y + l.z * wv.z + l.w * wv.w;
        }
        // tanh(x) = (e^{2x}-1)/(e^{2x}+1), accurate (__expf ~1 ulp), clamped
        float x = fminf(fmaxf(acc, -15.f), 15.f);
        float ex = __expf(2.f * x);
        float contrib = va * __fdividef(ex - 1.f, ex + 1.f);
#pragma unroll
        for (int off = 16; off; off >>= 1)
            contrib += __shfl_xor_sync(0xffffffffu, contrib, off);
        if (lane == 0) s_part[w][t] = contrib;
    }
    __syncthreads();
    {
        int t = tid;
        float e = s_part[0][t] + s_part[1][t] + s_part[2][t] + s_part[3][t];
        if (mask[(size_t)b * T_ + t0 + t] != 0) e = -CUDART_INF_F;
        g_energy[b * T_ + t0 + t] = e;
    }
}

// ---------------------------------------------------------------------------
// K3: softmax (recomputed per block, cheap) + context matvec + weights output.
// grid (8, B): 64 output dims per block, 256 threads (4-way t-split).
// ---------------------------------------------------------------------------
__global__ __launch_bounds__(256) void k_context(const float* __restrict__ mem,
                                                 float* __restrict__ out) {
    const int b = blockIdx.y;
    const int dchunk = blockIdx.x;  // 0..7
    const int tid = threadIdx.x;

    __shared__ float s_p[T_];
    __shared__ float s_red[8];
    __shared__ float s_acc[256];

    // load energies + local max
    float lmax = -CUDART_INF_F;
    for (int i = tid; i < T_; i += 256) {
        float e = g_energy[b * T_ + i];
        s_p[i] = e;
        lmax = fmaxf(lmax, e);
    }
#pragma unroll
    for (int off = 16; off; off >>= 1)
        lmax = fmaxf(lmax, __shfl_xor_sync(0xffffffffu, lmax, off));
    if ((tid & 31) == 0) s_red[tid >> 5] = lmax;
    __syncthreads();
    float bmax = s_red[0];
#pragma unroll
    for (int i = 1; i < 8; i++) bmax = fmaxf(bmax, s_red[i]);
    __syncthreads();  // protect s_red before reuse

    // exp + local sum
    float lsum = 0.f;
    for (int i = tid; i < T_; i += 256) {
        float p = __expf(s_p[i] - bmax);
        s_p[i] = p;
        lsum += p;
    }
#pragma unroll
    for (int off = 16; off; off >>= 1)
        lsum += __shfl_xor_sync(0xffffffffu, lsum, off);
    if ((tid & 31) == 0) s_red[tid >> 5] = lsum;
    __syncthreads();  // also orders s_p exp-writes before matvec
    float bsum = 0.f;
#pragma unroll
    for (int i = 0; i < 8; i++) bsum += s_red[i];
    float inv = 1.f / bsum;

    // context: ctx[b,d] = inv * sum_t p[t] * mem[b,t,d]
    const int q = tid >> 6;          // 0..3 (t phase)
    const int d = dchunk * 64 + (tid & 63);
    const float* mp = mem + (size_t)(b * T_) * EMB_ + d;
    float acc = 0.f;
#pragma unroll 8
    for (int t = q; t < T_; t += 4)
        acc += s_p[t] * mp[(size_t)t * EMB_];
    s_acc[tid] = acc;
    __syncthreads();
    if (tid < 64) {
        float tot = s_acc[tid] + s_acc[tid + 64] + s_acc[tid + 128] + s_acc[tid + 192];
        out[b * EMB_ + dchunk * 64 + tid] = tot * inv;
    }
    // attention weights output (once per b)
    if (dchunk == 0) {
        for (int i = tid; i < T_; i += 256)
            out[B_ * EMB_ + b * T_ + i] = s_p[i] * inv;
    }
}

// ---------------------------------------------------------------------------
extern "C" void kernel_launch(void* const* d_in, const int* in_sizes, int n_in,
                              void* d_out, int out_size) {
    const float* query = (const float*)d_in[0];
    const float* pm    = (const float*)d_in[1];
    const float* cat   = (const float*)d_in[2];
    const int*   mask  = (const int*)d_in[3];
    const float* mem   = (const float*)d_in[4];
    const float* Wq    = (const float*)d_in[5];
    const float* cw    = (const float*)d_in[6];
    const float* Wl    = (const float*)d_in[7];
    const float* vw    = (const float*)d_in[8];
    float* out = (float*)d_out;

    k_query<<<B_, 256>>>(query, Wq);
    dim3 g2(T_ / TILE_, B_);
    k_energy<<<g2, 128>>>(pm, cat, mask, cw, Wl, vw);
    dim3 g3(8, B_);
    k_context<<<g3, 256>>>(mem, out);
}

// round 6
// speedup vs baseline: 1.2170x; 1.2170x over previous
#include <cuda_runtime.h>
#include <math_constants.h>

#define B_      64
#define T_      2048
#define RNN_    1024
#define EMB_    512
#define ATT_    128
#define NF_     32
#define KS_     31
#define PAD_    15
#define TILE_   128

// scratch (no allocs allowed)
__device__ float g_pq[B_ * ATT_];       // processed query [B,128]
__device__ float g_energy[B_ * T_];     // pre-softmax energies [B,T]

// ---------------------------------------------------------------------------
// K1: g_pq[b,a] = sum_r query[b,r] * W_query[a,r]
// one warp per output; 1024 blocks x 256 threads (8 warps)
// ---------------------------------------------------------------------------
__global__ __launch_bounds__(256) void k_query(const float* __restrict__ q,
                                               const float* __restrict__ Wq) {
    const int warp = (blockIdx.x << 3) + (threadIdx.x >> 5);  // 0..8191
    const int lane = threadIdx.x & 31;
    const int b = warp >> 7;
    const int a = warp & 127;
    const float4* w4 = reinterpret_cast<const float4*>(Wq + (size_t)a * RNN_);
    const float4* q4 = reinterpret_cast<const float4*>(q + (size_t)b * RNN_);
    float acc = 0.f;
#pragma unroll
    for (int j = 0; j < 8; j++) {
        float4 w = w4[j * 32 + lane];
        float4 x = q4[j * 32 + lane];
        acc += w.x * x.x + w.y * x.y + w.z * x.z + w.w * x.w;
    }
#pragma unroll
    for (int off = 16; off; off >>= 1)
        acc += __shfl_xor_sync(0xffffffffu, acc, off);
    if (lane == 0) g_pq[warp] = acc;
}

// ---------------------------------------------------------------------------
// K2: energies. grid (T/TILE, B), 128 threads (thread = attention dim a).
// Fuses: conv(attn_weights_cat) -> loc; loc @ W_loc; + pm + pq; tanh; dot v;
// mask -> -inf; writes g_energy.
// ---------------------------------------------------------------------------
__global__ __launch_bounds__(128) void k_energy(const float* __restrict__ pm,
                                                const float* __restrict__ cat,
                                                const int* __restrict__ mask,
                                                const float* __restrict__ cw,
                                                const float* __restrict__ Wl,
                                                const float* __restrict__ vw) {
    const int b = blockIdx.y;
    const int t0 = blockIdx.x * TILE_;
    const int tid = threadIdx.x;

    __shared__ __align__(16) float s_cat[2][TILE_ + 32];    // window + zero pad
    __shared__ __align__(16) float s_cw[2][NF_][32];        // [c][f][k], k padded to 32
    __shared__ float4 s_loc[8][TILE_];                      // [f-group][t] -> f=4j..4j+3
    __shared__ float s_part[32][TILE_];                     // [w*8+g][t] partials

    // load input window (with boundary + tail zero padding)
#pragma unroll
    for (int c = 0; c < 2; c++) {
        for (int i = tid; i < TILE_ + 32; i += 128) {
            int g = t0 - PAD_ + i;
            float v = 0.f;
            if (i < TILE_ + 2 * PAD_ && g >= 0 && g < T_)
                v = cat[((size_t)(b * 2 + c)) * T_ + g];
            s_cat[c][i] = v;
        }
    }
    // load conv weights transposed [c][f][k], pad k=31 with 0
    for (int i = tid; i < 2 * NF_ * 32; i += 128) {
        int c = i >> 10;
        int f = (i >> 5) & 31;
        int k = i & 31;
        s_cw[c][f][k] = (k < KS_) ? cw[(f * 2 + c) * KS_ + k] : 0.f;
    }
    __syncthreads();

    // ---- conv phase: thread = local time index t=tid, 32 filters ----
    {
        float xr0[32], xr1[32];
#pragma unroll
        for (int i = 0; i < 32; i++) {
            xr0[i] = s_cat[0][tid + i];
            xr1[i] = s_cat[1][tid + i];
        }
#pragma unroll
        for (int j = 0; j < 8; j++) {
            float a0 = 0.f, a1 = 0.f, a2 = 0.f, a3 = 0.f;
#pragma unroll
            for (int kk = 0; kk < 8; kk++) {
                float x0 = xr0[4 * kk + 0], x1 = xr0[4 * kk + 1];
                float x2 = xr0[4 * kk + 2], x3 = xr0[4 * kk + 3];
                float4 w0 = *reinterpret_cast<const float4*>(&s_cw[0][4 * j + 0][4 * kk]);
                float4 w1 = *reinterpret_cast<const float4*>(&s_cw[0][4 * j + 1][4 * kk]);
                float4 w2 = *reinterpret_cast<const float4*>(&s_cw[0][4 * j + 2][4 * kk]);
                float4 w3 = *reinterpret_cast<const float4*>(&s_cw[0][4 * j + 3][4 * kk]);
                a0 += w0.x * x0 + w0.y * x1 + w0.z * x2 + w0.w * x3;
                a1 += w1.x * x0 + w1.y * x1 + w1.z * x2 + w1.w * x3;
                a2 += w2.x * x0 + w2.y * x1 + w2.z * x2 + w2.w * x3;
                a3 += w3.x * x0 + w3.y * x1 + w3.z * x2 + w3.w * x3;
                float y0 = xr1[4 * kk + 0], y1 = xr1[4 * kk + 1];
                float y2 = xr1[4 * kk + 2], y3 = xr1[4 * kk + 3];
                float4 u0 = *reinterpret_cast<const float4*>(&s_cw[1][4 * j + 0][4 * kk]);
                float4 u1 = *reinterpret_cast<const float4*>(&s_cw[1][4 * j + 1][4 * kk]);
                float4 u2 = *reinterpret_cast<const float4*>(&s_cw[1][4 * j + 2][4 * kk]);
                float4 u3 = *reinterpret_cast<const float4*>(&s_cw[1][4 * j + 3][4 * kk]);
                a0 += u0.x * y0 + u0.y * y1 + u0.z * y2 + u0.w * y3;
                a1 += u1.x * y0 + u1.y * y1 + u1.z * y2 + u1.w * y3;
                a2 += u2.x * y0 + u2.y * y1 + u2.z * y2 + u2.w * y3;
                a3 += u3.x * y0 + u3.y * y1 + u3.z * y2 + u3.w * y3;
            }
            s_loc[j][tid] = make_float4(a0, a1, a2, a3);
        }
    }
    __syncthreads();

    // ---- energies phase: thread = a, loop over t ----
    float4 wl4[8];
    {
        const float4* wlg = reinterpret_cast<const float4*>(Wl + tid * NF_);
#pragma unroll
        for (int j = 0; j < 8; j++) wl4[j] = wlg[j];
    }
    const float va = vw[tid];
    const float pqa = g_pq[b * ATT_ + tid];
    const int w = tid >> 5, lane = tid & 31;
    const float* pmb = pm + ((size_t)(b * T_ + t0)) * ATT_ + tid;

#pragma unroll 4
    for (int t = 0; t < TILE_; t++) {
        float acc = pqa + pmb[(size_t)t * ATT_];
#pragma unroll
        for (int j = 0; j < 8; j++) {
            float4 l = s_loc[j][t];
            float4 wv = wl4[j];
            acc += l.x * wv.x + l.y * wv.y + l.z * wv.z + l.w * wv.w;
        }
        float th;
        asm("tanh.approx.f32 %0, %1;" : "=f"(th) : "f"(acc));
        float contrib = va * th;
        contrib += __shfl_xor_sync(0xffffffffu, contrib, 16);
        contrib += __shfl_xor_sync(0xffffffffu, contrib, 8);
        // lane l (<8) now holds sum over lanes {l, l+8, l+16, l+24}
        if (lane < 8) s_part[w * 8 + lane][t] = contrib;
    }
    __syncthreads();
    {
        int t = tid;
        float e = 0.f;
#pragma unroll
        for (int i = 0; i < 32; i++) e += s_part[i][t];
        if (mask[(size_t)b * T_ + t0 + t] != 0) e = -CUDART_INF_F;
        g_energy[b * T_ + t0 + t] = e;
    }
}

// ---------------------------------------------------------------------------
// K3: softmax (recomputed per block, cheap) + context matvec + weights output.
// grid (4, B): 128 output dims per block (float2/thread), 256 threads,
// 4-way t-split.
// ---------------------------------------------------------------------------
__global__ __launch_bounds__(256) void k_context(const float* __restrict__ mem,
                                                 float* __restrict__ out) {
    const int b = blockIdx.y;
    const int dchunk = blockIdx.x;  // 0..3
    const int tid = threadIdx.x;

    __shared__ float s_p[T_];
    __shared__ float s_red[8];
    __shared__ float2 s_acc[256];

    // load energies + local max
    float lmax = -CUDART_INF_F;
    for (int i = tid; i < T_; i += 256) {
        float e = g_energy[b * T_ + i];
        s_p[i] = e;
        lmax = fmaxf(lmax, e);
    }
#pragma unroll
    for (int off = 16; off; off >>= 1)
        lmax = fmaxf(lmax, __shfl_xor_sync(0xffffffffu, lmax, off));
    if ((tid & 31) == 0) s_red[tid >> 5] = lmax;
    __syncthreads();
    float bmax = s_red[0];
#pragma unroll
    for (int i = 1; i < 8; i++) bmax = fmaxf(bmax, s_red[i]);
    __syncthreads();  // protect s_red before reuse

    // exp + local sum
    float lsum = 0.f;
    for (int i = tid; i < T_; i += 256) {
        float p = __expf(s_p[i] - bmax);
        s_p[i] = p;
        lsum += p;
    }
#pragma unroll
    for (int off = 16; off; off >>= 1)
        lsum += __shfl_xor_sync(0xffffffffu, lsum, off);
    if ((tid & 31) == 0) s_red[tid >> 5] = lsum;
    __syncthreads();  // also orders s_p exp-writes before matvec
    float bsum = 0.f;
#pragma unroll
    for (int i = 0; i < 8; i++) bsum += s_red[i];
    float inv = 1.f / bsum;

    // context: ctx[b,d:d+2] = inv * sum_t p[t] * mem[b,t,d:d+2]
    const int q = tid >> 6;          // 0..3 (t phase)
    const float2* mp = reinterpret_cast<const float2*>(
        mem + (size_t)(b * T_) * EMB_ + dchunk * 128) + (tid & 63);
    float2 a0 = make_float2(0.f, 0.f);
    float2 a1 = make_float2(0.f, 0.f);
#pragma unroll 4
    for (int t = q; t < T_; t += 8) {
        float p0 = s_p[t];
        float2 m0 = mp[(size_t)t * 256];
        float p1 = s_p[t + 4];
        float2 m1 = mp[(size_t)(t + 4) * 256];
        a0.x += p0 * m0.x; a0.y += p0 * m0.y;
        a1.x += p1 * m1.x; a1.y += p1 * m1.y;
    }
    a0.x += a1.x; a0.y += a1.y;
    s_acc[tid] = a0;
    __syncthreads();
    if (tid < 64) {
        float2 r0 = s_acc[tid];
        float2 r1 = s_acc[tid + 64];
        float2 r2 = s_acc[tid + 128];
        float2 r3 = s_acc[tid + 192];
        float2 tot = make_float2((r0.x + r1.x) + (r2.x + r3.x),
                                 (r0.y + r1.y) + (r2.y + r3.y));
        float2* o2 = reinterpret_cast<float2*>(out + b * EMB_ + dchunk * 128);
        o2[tid] = make_float2(tot.x * inv, tot.y * inv);
    }
    // attention weights output (once per b)
    if (dchunk == 0) {
        for (int i = tid; i < T_; i += 256)
            out[B_ * EMB_ + b * T_ + i] = s_p[i] * inv;
    }
}

// ---------------------------------------------------------------------------
extern "C" void kernel_launch(void* const* d_in, const int* in_sizes, int n_in,
                              void* d_out, int out_size) {
    const float* query = (const float*)d_in[0];
    const float* pm    = (const float*)d_in[1];
    const float* cat   = (const float*)d_in[2];
    const int*   mask  = (const int*)d_in[3];
    const float* mem   = (const float*)d_in[4];
    const float* Wq    = (const float*)d_in[5];
    const float* cw    = (const float*)d_in[6];
    const float* Wl    = (const float*)d_in[7];
    const float* vw    = (const float*)d_in[8];
    float* out = (float*)d_out;

    k_query<<<1024, 256>>>(query, Wq);
    dim3 g2(T_ / TILE_, B_);
    k_energy<<<g2, 128>>>(pm, cat, mask, cw, Wl, vw);
    dim3 g3(4, B_);
    k_context<<<g3, 256>>>(mem, out);
}

// round 10
// speedup vs baseline: 1.8916x; 1.5543x over previous
#include <cuda_runtime.h>
#include <math_constants.h>

#define B_      64
#define T_      2048
#define RNN_    1024
#define EMB_    512
#define ATT_    128
#define NF_     32
#define KS_     31
#define PAD_    15
#define TILE_   128

// scratch (no allocs allowed)
__device__ float g_pq[B_ * ATT_];       // processed query [B,128]
__device__ float g_energy[B_ * T_];     // pre-softmax energies [B,T]
__device__ float g_prob[B_ * T_];       // normalized attention weights [B,T]

// ---------------------------------------------------------------------------
// K1: g_pq[b,a] = sum_r query[b,r] * W_query[a,r]
// grid 512: block = (b, chunk of 16 a). q staged in smem; each Wq row read
// exactly once chip-wide. 8 warps x 2 outputs per warp.
// ---------------------------------------------------------------------------
__global__ __launch_bounds__(256) void k_query(const float* __restrict__ q,
                                               const float* __restrict__ Wq) {
    const int b = blockIdx.x >> 3;
    const int ch = blockIdx.x & 7;
    const int tid = threadIdx.x;
    const int w = tid >> 5, lane = tid & 31;
    __shared__ float4 s_q[256];
    s_q[tid] = reinterpret_cast<const float4*>(q + (size_t)b * RNN_)[tid];
    __syncthreads();
    const int a0 = ch * 16 + w * 2;
    const float4* w0 = reinterpret_cast<const float4*>(Wq + (size_t)a0 * RNN_);
    const float4* w1 = w0 + 256;
    float acc0 = 0.f, acc1 = 0.f;
#pragma unroll
    for (int j = 0; j < 8; j++) {
        float4 x = s_q[j * 32 + lane];
        float4 u = w0[j * 32 + lane];
        float4 v = w1[j * 32 + lane];
        acc0 += u.x * x.x + u.y * x.y + u.z * x.z + u.w * x.w;
        acc1 += v.x * x.x + v.y * x.y + v.z * x.z + v.w * x.w;
    }
#pragma unroll
    for (int off = 16; off; off >>= 1) {
        acc0 += __shfl_xor_sync(0xffffffffu, acc0, off);
        acc1 += __shfl_xor_sync(0xffffffffu, acc1, off);
    }
    if (lane == 0) {
        g_pq[b * ATT_ + a0] = acc0;
        g_pq[b * ATT_ + a0 + 1] = acc1;
    }
}

// ---------------------------------------------------------------------------
// K2: energies. grid (16, 64), 128 threads; thread = local time index t.
// conv results loc[32] live in registers; loop over a with W_loc broadcast
// from smem and pm staged in 32-a chunks. No cross-thread reduction at all.
// ---------------------------------------------------------------------------
__global__ __launch_bounds__(128, 5) void k_energy(const float* __restrict__ pm,
                                                   const float* __restrict__ cat,
                                                   const int* __restrict__ mask,
                                                   const float* __restrict__ cw,
                                                   const float* __restrict__ Wl,
                                                   const float* __restrict__ vw) {
    const int b = blockIdx.y;
    const int t0 = blockIdx.x * TILE_;
    const int tid = threadIdx.x;

    __shared__ float s_cat[2][TILE_ + 32];                  // 1.25 KB
    __shared__ __align__(16) float s_cw[2][NF_][32];        // 8 KB [c][f][k]
    __shared__ float4 s_wl[ATT_][8];                        // 16 KB Wl[a][f/4]
    __shared__ float s_pq[ATT_];
    __shared__ float s_v[ATT_];
    __shared__ float s_pm[TILE_ * 33];                      // 16.9 KB (pad 33)

    // stage conv input window (zero pad at boundaries + tail)
#pragma unroll
    for (int c = 0; c < 2; c++) {
        for (int i = tid; i < TILE_ + 32; i += 128) {
            int g = t0 - PAD_ + i;
            float v = 0.f;
            if (i < TILE_ + 2 * PAD_ && g >= 0 && g < T_)
                v = cat[((size_t)(b * 2 + c)) * T_ + g];
            s_cat[c][i] = v;
        }
    }
    // conv weights transposed [c][f][k], k padded to 32 with 0
    for (int i = tid; i < 2 * NF_ * 32; i += 128) {
        int c = i >> 10;
        int f = (i >> 5) & 31;
        int k = i & 31;
        s_cw[c][f][k] = (k < KS_) ? cw[(f * 2 + c) * KS_ + k] : 0.f;
    }
    // W_loc [128 a][32 f] -> smem as float4
    for (int i = tid; i < ATT_ * 8; i += 128)
        reinterpret_cast<float4*>(s_wl)[i] = reinterpret_cast<const float4*>(Wl)[i];
    s_pq[tid] = g_pq[b * ATT_ + tid];
    s_v[tid] = vw[tid];
    __syncthreads();

    // ---- conv: loc[0..31] in registers, one channel at a time ----
    float loc[NF_];
#pragma unroll
    for (int i = 0; i < NF_; i++) loc[i] = 0.f;
#pragma unroll
    for (int c = 0; c < 2; c++) {
        float xr[32];
#pragma unroll
        for (int i = 0; i < 32; i++) xr[i] = s_cat[c][tid + i];
#pragma unroll
        for (int j = 0; j < NF_; j++) {
            float a = 0.f;
#pragma unroll
            for (int kk = 0; kk < 8; kk++) {
                float4 w = *reinterpret_cast<const float4*>(&s_cw[c][j][4 * kk]);
                a += w.x * xr[4 * kk] + w.y * xr[4 * kk + 1] +
                     w.z * xr[4 * kk + 2] + w.w * xr[4 * kk + 3];
            }
            loc[j] += a;
        }
    }

    // ---- energies: e[t] = sum_a v[a] * tanh(pq[a] + pm[t,a] + Wl[a,:].loc) ----
    float e = 0.f;
#pragma unroll
    for (int chv = 0; chv < 4; chv++) {
        // stage pm tile [128 t][32 a] into padded smem.
        // NOTE: stride 33 floats => odd-t rows are NOT 16B-aligned, so the
        // store side MUST be scalar (STS.128 here traps: misaligned address).
        // Scalar store banks: (33t+4a4+k)%32 = (t+4a4+k)%32 -> conflict-free.
        __syncthreads();
#pragma unroll
        for (int r = 0; r < 8; r++) {
            int i = r * 128 + tid;          // 0..1023 float4s
            int t = i >> 3, a4 = i & 7;
            float4 v4 = *reinterpret_cast<const float4*>(
                pm + ((size_t)(b * T_) + t0 + t) * ATT_ + chv * 32 + a4 * 4);
            float* dst = &s_pm[t * 33 + a4 * 4];
            dst[0] = v4.x; dst[1] = v4.y; dst[2] = v4.z; dst[3] = v4.w;
        }
        __syncthreads();
#pragma unroll 4
        for (int aa = 0; aa < 32; aa++) {
            int a = chv * 32 + aa;
            float z = s_pq[a] + s_pm[tid * 33 + aa];
#pragma unroll
            for (int j = 0; j < 8; j++) {
                float4 w = s_wl[a][j];
                z += w.x * loc[4 * j] + w.y * loc[4 * j + 1] +
                     w.z * loc[4 * j + 2] + w.w * loc[4 * j + 3];
            }
            float th;
            asm("tanh.approx.f32 %0, %1;" : "=f"(th) : "f"(z));
            e += s_v[a] * th;
        }
    }
    const int gt = b * T_ + t0 + tid;
    if (mask[gt] != 0) e = -CUDART_INF_F;
    g_energy[gt] = e;
}

// ---------------------------------------------------------------------------
// K3a: softmax over T per b. 64 blocks x 256 threads; 8 energies per thread
// held in registers across passes. Writes normalized probs to g_prob AND the
// attention-weights output slice.
// ---------------------------------------------------------------------------
__global__ __launch_bounds__(256) void k_softmax(float* __restrict__ out) {
    const int b = blockIdx.x;
    const int tid = threadIdx.x;
    __shared__ float s_red[8];

    float4 e0 = reinterpret_cast<const float4*>(g_energy + b * T_)[tid * 2];
    float4 e1 = reinterpret_cast<const float4*>(g_energy + b * T_)[tid * 2 + 1];

    float lmax = fmaxf(fmaxf(fmaxf(e0.x, e0.y), fmaxf(e0.z, e0.w)),
                       fmaxf(fmaxf(e1.x, e1.y), fmaxf(e1.z, e1.w)));
#pragma unroll
    for (int off = 16; off; off >>= 1)
        lmax = fmaxf(lmax, __shfl_xor_sync(0xffffffffu, lmax, off));
    if ((tid & 31) == 0) s_red[tid >> 5] = lmax;
    __syncthreads();
    float bmax = s_red[0];
#pragma unroll
    for (int i = 1; i < 8; i++) bmax = fmaxf(bmax, s_red[i]);
    __syncthreads();

    float4 p0 = make_float4(__expf(e0.x - bmax), __expf(e0.y - bmax),
                            __expf(e0.z - bmax), __expf(e0.w - bmax));
    float4 p1 = make_float4(__expf(e1.x - bmax), __expf(e1.y - bmax),
                            __expf(e1.z - bmax), __expf(e1.w - bmax));
    float lsum = (p0.x + p0.y) + (p0.z + p0.w) + (p1.x + p1.y) + (p1.z + p1.w);
#pragma unroll
    for (int off = 16; off; off >>= 1)
        lsum += __shfl_xor_sync(0xffffffffu, lsum, off);
    if ((tid & 31) == 0) s_red[tid >> 5] = lsum;
    __syncthreads();
    float bsum = 0.f;
#pragma unroll
    for (int i = 0; i < 8; i++) bsum += s_red[i];
    const float inv = 1.f / bsum;

    p0.x *= inv; p0.y *= inv; p0.z *= inv; p0.w *= inv;
    p1.x *= inv; p1.y *= inv; p1.z *= inv; p1.w *= inv;
    reinterpret_cast<float4*>(g_prob + b * T_)[tid * 2] = p0;
    reinterpret_cast<float4*>(g_prob + b * T_)[tid * 2 + 1] = p1;
    float* ow = out + B_ * EMB_ + b * T_;
    reinterpret_cast<float4*>(ow)[tid * 2] = p0;
    reinterpret_cast<float4*>(ow)[tid * 2 + 1] = p1;
}

// ---------------------------------------------------------------------------
// K3b: context matvec. grid (4, B), 512 threads = 8 t-phases x 64 d (float2).
// Explicit 8-deep load batching for DRAM MLP.
// ---------------------------------------------------------------------------
__global__ __launch_bounds__(512) void k_ctx(const float* __restrict__ mem,
                                             float* __restrict__ out) {
    const int b = blockIdx.y;
    const int dc = blockIdx.x;      // 0..3 -> 128 dims each
    const int tid = threadIdx.x;

    __shared__ float s_p[T_];
    __shared__ float2 s_acc[512];

    reinterpret_cast<float4*>(s_p)[tid] =
        reinterpret_cast<const float4*>(g_prob + b * T_)[tid];
    __syncthreads();

    const int ph = tid >> 6;        // 0..7
    const float2* mp = reinterpret_cast<const float2*>(
        mem + (size_t)b * T_ * EMB_ + dc * 128) + (tid & 63);
    float2 acc = make_float2(0.f, 0.f);
    for (int tb = ph; tb < T_; tb += 64) {
        float2 r[8];
#pragma unroll
        for (int u = 0; u < 8; u++) r[u] = mp[(size_t)(tb + u * 8) * 256];
#pragma unroll
        for (int u = 0; u < 8; u++) {
            float p = s_p[tb + u * 8];
            acc.x += p * r[u].x;
            acc.y += p * r[u].y;
        }
    }
    s_acc[tid] = acc;
    __syncthreads();
    if (tid < 64) {
        float2 tot = make_float2(0.f, 0.f);
#pragma unroll
        for (int k = 0; k < 8; k++) {
            float2 v = s_acc[k * 64 + tid];
            tot.x += v.x;
            tot.y += v.y;
        }
        reinterpret_cast<float2*>(out + b * EMB_ + dc * 128)[tid] = tot;
    }
}

// ---------------------------------------------------------------------------
extern "C" void kernel_launch(void* const* d_in, const int* in_sizes, int n_in,
                              void* d_out, int out_size) {
    const float* query = (const float*)d_in[0];
    const float* pm    = (const float*)d_in[1];
    const float* cat   = (const float*)d_in[2];
    const int*   mask  = (const int*)d_in[3];
    const float* mem   = (const float*)d_in[4];
    const float* Wq    = (const float*)d_in[5];
    const float* cw    = (const float*)d_in[6];
    const float* Wl    = (const float*)d_in[7];
    const float* vw    = (const float*)d_in[8];
    float* out = (float*)d_out;

    k_query<<<512, 256>>>(query, Wq);
    dim3 g2(T_ / TILE_, B_);
    k_energy<<<g2, 128>>>(pm, cat, mask, cw, Wl, vw);
    k_softmax<<<B_, 256>>>(out);
    dim3 g3(4, B_);
    k_ctx<<<g3, 512>>>(mem, out);
}

// round 11
// speedup vs baseline: 1.9026x; 1.0058x over previous
#include <cuda_runtime.h>
#include <math_constants.h>

#define B_      64
#define T_      2048
#define RNN_    1024
#define EMB_    512
#define ATT_    128
#define NF_     32
#define KS_     31
#define PAD_    15
#define TILE_   128

// scratch (no allocs allowed)
__device__ float g_pq[B_ * ATT_];       // processed query [B,128]
__device__ float g_energy[B_ * T_];     // pre-softmax energies [B,T]
__device__ float g_prob[B_ * T_];       // normalized attention weights [B,T]

// ---------------------------------------------------------------------------
// K1: g_pq[b,a] = sum_r query[b,r] * W_query[a,r]
// grid 512: block = (b, chunk of 16 a). q staged in smem; each Wq row read
// exactly once chip-wide. 8 warps x 2 outputs per warp.
// ---------------------------------------------------------------------------
__global__ __launch_bounds__(256) void k_query(const float* __restrict__ q,
                                               const float* __restrict__ Wq) {
    const int b = blockIdx.x >> 3;
    const int ch = blockIdx.x & 7;
    const int tid = threadIdx.x;
    const int w = tid >> 5, lane = tid & 31;
    __shared__ float4 s_q[256];
    s_q[tid] = reinterpret_cast<const float4*>(q + (size_t)b * RNN_)[tid];
    __syncthreads();
    const int a0 = ch * 16 + w * 2;
    const float4* w0 = reinterpret_cast<const float4*>(Wq + (size_t)a0 * RNN_);
    const float4* w1 = w0 + 256;
    float acc0 = 0.f, acc1 = 0.f;
#pragma unroll
    for (int j = 0; j < 8; j++) {
        float4 x = s_q[j * 32 + lane];
        float4 u = w0[j * 32 + lane];
        float4 v = w1[j * 32 + lane];
        acc0 += u.x * x.x + u.y * x.y + u.z * x.z + u.w * x.w;
        acc1 += v.x * x.x + v.y * x.y + v.z * x.z + v.w * x.w;
    }
#pragma unroll
    for (int off = 16; off; off >>= 1) {
        acc0 += __shfl_xor_sync(0xffffffffu, acc0, off);
        acc1 += __shfl_xor_sync(0xffffffffu, acc1, off);
    }
    if (lane == 0) {
        g_pq[b * ATT_ + a0] = acc0;
        g_pq[b * ATT_ + a0 + 1] = acc1;
    }
}

// ---------------------------------------------------------------------------
// K2: energies. grid (16, 64), 128 threads; thread = local time index t.
// conv results loc[32] live in registers; loop over a with W_loc broadcast
// from smem and pm staged in 32-a chunks. No cross-thread reduction at all.
// ---------------------------------------------------------------------------
__global__ __launch_bounds__(128, 5) void k_energy(const float* __restrict__ pm,
                                                   const float* __restrict__ cat,
                                                   const int* __restrict__ mask,
                                                   const float* __restrict__ cw,
                                                   const float* __restrict__ Wl,
                                                   const float* __restrict__ vw) {
    const int b = blockIdx.y;
    const int t0 = blockIdx.x * TILE_;
    const int tid = threadIdx.x;

    __shared__ float s_cat[2][TILE_ + 32];                  // 1.25 KB
    __shared__ __align__(16) float s_cw[2][NF_][32];        // 8 KB [c][f][k]
    __shared__ float4 s_wl[ATT_][8];                        // 16 KB Wl[a][f/4]
    __shared__ float s_pq[ATT_];
    __shared__ float s_v[ATT_];
    __shared__ float s_pm[TILE_ * 33];                      // 16.9 KB (pad 33)

    // stage conv input window (zero pad at boundaries + tail)
#pragma unroll
    for (int c = 0; c < 2; c++) {
        for (int i = tid; i < TILE_ + 32; i += 128) {
            int g = t0 - PAD_ + i;
            float v = 0.f;
            if (i < TILE_ + 2 * PAD_ && g >= 0 && g < T_)
                v = cat[((size_t)(b * 2 + c)) * T_ + g];
            s_cat[c][i] = v;
        }
    }
    // conv weights transposed [c][f][k], k padded to 32 with 0
    for (int i = tid; i < 2 * NF_ * 32; i += 128) {
        int c = i >> 10;
        int f = (i >> 5) & 31;
        int k = i & 31;
        s_cw[c][f][k] = (k < KS_) ? cw[(f * 2 + c) * KS_ + k] : 0.f;
    }
    // W_loc [128 a][32 f] -> smem as float4
    for (int i = tid; i < ATT_ * 8; i += 128)
        reinterpret_cast<float4*>(s_wl)[i] = reinterpret_cast<const float4*>(Wl)[i];
    s_pq[tid] = g_pq[b * ATT_ + tid];
    s_v[tid] = vw[tid];
    __syncthreads();

    // ---- conv: loc[0..31] in registers, one channel at a time ----
    float loc[NF_];
#pragma unroll
    for (int i = 0; i < NF_; i++) loc[i] = 0.f;
#pragma unroll
    for (int c = 0; c < 2; c++) {
        float xr[32];
#pragma unroll
        for (int i = 0; i < 32; i++) xr[i] = s_cat[c][tid + i];
#pragma unroll
        for (int j = 0; j < NF_; j++) {
            float a = 0.f;
#pragma unroll
            for (int kk = 0; kk < 8; kk++) {
                float4 w = *reinterpret_cast<const float4*>(&s_cw[c][j][4 * kk]);
                a += w.x * xr[4 * kk] + w.y * xr[4 * kk + 1] +
                     w.z * xr[4 * kk + 2] + w.w * xr[4 * kk + 3];
            }
            loc[j] += a;
        }
    }

    // ---- energies: e[t] = sum_a v[a] * tanh(pq[a] + pm[t,a] + Wl[a,:].loc) ----
    float e = 0.f;
#pragma unroll
    for (int chv = 0; chv < 4; chv++) {
        // stage pm tile [128 t][32 a] into padded smem.
        // NOTE: stride 33 floats => odd-t rows are NOT 16B-aligned, so the
        // store side MUST be scalar (STS.128 here traps: misaligned address).
        // Scalar store banks: (33t+4a4+k)%32 = (t+4a4+k)%32 -> conflict-free.
        __syncthreads();
#pragma unroll
        for (int r = 0; r < 8; r++) {
            int i = r * 128 + tid;          // 0..1023 float4s
            int t = i >> 3, a4 = i & 7;
            float4 v4 = *reinterpret_cast<const float4*>(
                pm + ((size_t)(b * T_) + t0 + t) * ATT_ + chv * 32 + a4 * 4);
            float* dst = &s_pm[t * 33 + a4 * 4];
            dst[0] = v4.x; dst[1] = v4.y; dst[2] = v4.z; dst[3] = v4.w;
        }
        __syncthreads();
#pragma unroll 4
        for (int aa = 0; aa < 32; aa++) {
            int a = chv * 32 + aa;
            float z = s_pq[a] + s_pm[tid * 33 + aa];
#pragma unroll
            for (int j = 0; j < 8; j++) {
                float4 w = s_wl[a][j];
                z += w.x * loc[4 * j] + w.y * loc[4 * j + 1] +
                     w.z * loc[4 * j + 2] + w.w * loc[4 * j + 3];
            }
            float th;
            asm("tanh.approx.f32 %0, %1;" : "=f"(th) : "f"(z));
            e += s_v[a] * th;
        }
    }
    const int gt = b * T_ + t0 + tid;
    if (mask[gt] != 0) e = -CUDART_INF_F;
    g_energy[gt] = e;
}

// ---------------------------------------------------------------------------
// K3a: softmax over T per b. 64 blocks x 256 threads; 8 energies per thread
// held in registers across passes. Writes normalized probs to g_prob AND the
// attention-weights output slice.
// ---------------------------------------------------------------------------
__global__ __launch_bounds__(256) void k_softmax(float* __restrict__ out) {
    const int b = blockIdx.x;
    const int tid = threadIdx.x;
    __shared__ float s_red[8];

    float4 e0 = reinterpret_cast<const float4*>(g_energy + b * T_)[tid * 2];
    float4 e1 = reinterpret_cast<const float4*>(g_energy + b * T_)[tid * 2 + 1];

    float lmax = fmaxf(fmaxf(fmaxf(e0.x, e0.y), fmaxf(e0.z, e0.w)),
                       fmaxf(fmaxf(e1.x, e1.y), fmaxf(e1.z, e1.w)));
#pragma unroll
    for (int off = 16; off; off >>= 1)
        lmax = fmaxf(lmax, __shfl_xor_sync(0xffffffffu, lmax, off));
    if ((tid & 31) == 0) s_red[tid >> 5] = lmax;
    __syncthreads();
    float bmax = s_red[0];
#pragma unroll
    for (int i = 1; i < 8; i++) bmax = fmaxf(bmax, s_red[i]);
    __syncthreads();

    float4 p0 = make_float4(__expf(e0.x - bmax), __expf(e0.y - bmax),
                            __expf(e0.z - bmax), __expf(e0.w - bmax));
    float4 p1 = make_float4(__expf(e1.x - bmax), __expf(e1.y - bmax),
                            __expf(e1.z - bmax), __expf(e1.w - bmax));
    float lsum = (p0.x + p0.y) + (p0.z + p0.w) + (p1.x + p1.y) + (p1.z + p1.w);
#pragma unroll
    for (int off = 16; off; off >>= 1)
        lsum += __shfl_xor_sync(0xffffffffu, lsum, off);
    if ((tid & 31) == 0) s_red[tid >> 5] = lsum;
    __syncthreads();
    float bsum = 0.f;
#pragma unroll
    for (int i = 0; i < 8; i++) bsum += s_red[i];
    const float inv = 1.f / bsum;

    p0.x *= inv; p0.y *= inv; p0.z *= inv; p0.w *= inv;
    p1.x *= inv; p1.y *= inv; p1.z *= inv; p1.w *= inv;
    reinterpret_cast<float4*>(g_prob + b * T_)[tid * 2] = p0;
    reinterpret_cast<float4*>(g_prob + b * T_)[tid * 2 + 1] = p1;
    float* ow = out + B_ * EMB_ + b * T_;
    reinterpret_cast<float4*>(ow)[tid * 2] = p0;
    reinterpret_cast<float4*>(ow)[tid * 2 + 1] = p1;
}

// ---------------------------------------------------------------------------
// K3b: context matvec. grid (4, B), 512 threads = 8 t-phases x 64 d (float2).
// Explicit 8-deep load batching for DRAM MLP.
// ---------------------------------------------------------------------------
__global__ __launch_bounds__(512) void k_ctx(const float* __restrict__ mem,
                                             float* __restrict__ out) {
    const int b = blockIdx.y;
    const int dc = blockIdx.x;      // 0..3 -> 128 dims each
    const int tid = threadIdx.x;

    __shared__ float s_p[T_];
    __shared__ float2 s_acc[512];

    reinterpret_cast<float4*>(s_p)[tid] =
        reinterpret_cast<const float4*>(g_prob + b * T_)[tid];
    __syncthreads();

    const int ph = tid >> 6;        // 0..7
    const float2* mp = reinterpret_cast<const float2*>(
        mem + (size_t)b * T_ * EMB_ + dc * 128) + (tid & 63);
    float2 acc = make_float2(0.f, 0.f);
    for (int tb = ph; tb < T_; tb += 64) {
        float2 r[8];
#pragma unroll
        for (int u = 0; u < 8; u++) r[u] = mp[(size_t)(tb + u * 8) * 256];
#pragma unroll
        for (int u = 0; u < 8; u++) {
            float p = s_p[tb + u * 8];
            acc.x += p * r[u].x;
            acc.y += p * r[u].y;
        }
    }
    s_acc[tid] = acc;
    __syncthreads();
    if (tid < 64) {
        float2 tot = make_float2(0.f, 0.f);
#pragma unroll
        for (int k = 0; k < 8; k++) {
            float2 v = s_acc[k * 64 + tid];
            tot.x += v.x;
            tot.y += v.y;
        }
        reinterpret_cast<float2*>(out + b * EMB_ + dc * 128)[tid] = tot;
    }
}

// ---------------------------------------------------------------------------
extern "C" void kernel_launch(void* const* d_in, const int* in_sizes, int n_in,
                              void* d_out, int out_size) {
    const float* query = (const float*)d_in[0];
    const float* pm    = (const float*)d_in[1];
    const float* cat   = (const float*)d_in[2];
    const int*   mask  = (const int*)d_in[3];
    const float* mem   = (const float*)d_in[4];
    const float* Wq    = (const float*)d_in[5];
    const float* cw    = (const float*)d_in[6];
    const float* Wl    = (const float*)d_in[7];
    const float* vw    = (const float*)d_in[8];
    float* out = (float*)d_out;

    k_query<<<512, 256>>>(query, Wq);
    dim3 g2(T_ / TILE_, B_);
    k_energy<<<g2, 128>>>(pm, cat, mask, cw, Wl, vw);
    k_softmax<<<B_, 256>>>(out);
    dim3 g3(4, B_);
    k_ctx<<<g3, 512>>>(mem, out);
}

// round 12
// speedup vs baseline: 1.9143x; 1.0061x over previous
#include <cuda_runtime.h>
#include <math_constants.h>

#define B_      64
#define T_      2048
#define RNN_    1024
#define EMB_    512
#define ATT_    128
#define NF_     32
#define KS_     31
#define PAD_    15
#define TILE_   128

// scratch (no allocs allowed)
__device__ float g_pq[B_ * ATT_];       // processed query [B,128]
__device__ float g_energy[B_ * T_];     // pre-softmax energies [B,T]
__device__ float g_prob[B_ * T_];       // normalized attention weights [B,T]

// ---------------------------------------------------------------------------
// K1: g_pq[b,a] = sum_r query[b,r] * W_query[a,r]
// grid 512: block = (b, chunk of 16 a). q staged in smem; each Wq row read
// exactly once chip-wide. 8 warps x 2 outputs per warp.
// ---------------------------------------------------------------------------
__global__ __launch_bounds__(256) void k_query(const float* __restrict__ q,
                                               const float* __restrict__ Wq) {
    const int b = blockIdx.x >> 3;
    const int ch = blockIdx.x & 7;
    const int tid = threadIdx.x;
    const int w = tid >> 5, lane = tid & 31;
    __shared__ float4 s_q[256];
    s_q[tid] = reinterpret_cast<const float4*>(q + (size_t)b * RNN_)[tid];
    __syncthreads();
    const int a0 = ch * 16 + w * 2;
    const float4* w0 = reinterpret_cast<const float4*>(Wq + (size_t)a0 * RNN_);
    const float4* w1 = w0 + 256;
    float acc0 = 0.f, acc1 = 0.f;
#pragma unroll
    for (int j = 0; j < 8; j++) {
        float4 x = s_q[j * 32 + lane];
        float4 u = w0[j * 32 + lane];
        float4 v = w1[j * 32 + lane];
        acc0 += u.x * x.x + u.y * x.y + u.z * x.z + u.w * x.w;
        acc1 += v.x * x.x + v.y * x.y + v.z * x.z + v.w * x.w;
    }
#pragma unroll
    for (int off = 16; off; off >>= 1) {
        acc0 += __shfl_xor_sync(0xffffffffu, acc0, off);
        acc1 += __shfl_xor_sync(0xffffffffu, acc1, off);
    }
    if (lane == 0) {
        g_pq[b * ATT_ + a0] = acc0;
        g_pq[b * ATT_ + a0 + 1] = acc1;
    }
}

// ---------------------------------------------------------------------------
// K2: energies. grid (16, 64), 128 threads; thread = local time index t.
// conv results loc[32] live in registers; loop over a with W_loc broadcast
// from smem and pm staged in 32-a chunks. No cross-thread reduction at all.
// ---------------------------------------------------------------------------
__global__ __launch_bounds__(128, 5) void k_energy(const float* __restrict__ pm,
                                                   const float* __restrict__ cat,
                                                   const int* __restrict__ mask,
                                                   const float* __restrict__ cw,
                                                   const float* __restrict__ Wl,
                                                   const float* __restrict__ vw) {
    const int b = blockIdx.y;
    const int t0 = blockIdx.x * TILE_;
    const int tid = threadIdx.x;

    __shared__ float s_cat[2][TILE_ + 32];                  // 1.25 KB
    __shared__ __align__(16) float s_cw[2][NF_][32];        // 8 KB [c][f][k]
    __shared__ float4 s_wl[ATT_][8];                        // 16 KB Wl[a][f/4]
    __shared__ float s_pq[ATT_];
    __shared__ float s_v[ATT_];
    __shared__ float s_pm[TILE_ * 33];                      // 16.9 KB (pad 33)

    // stage conv input window (zero pad at boundaries + tail)
#pragma unroll
    for (int c = 0; c < 2; c++) {
        for (int i = tid; i < TILE_ + 32; i += 128) {
            int g = t0 - PAD_ + i;
            float v = 0.f;
            if (i < TILE_ + 2 * PAD_ && g >= 0 && g < T_)
                v = cat[((size_t)(b * 2 + c)) * T_ + g];
            s_cat[c][i] = v;
        }
    }
    // conv weights transposed [c][f][k], k padded to 32 with 0
    for (int i = tid; i < 2 * NF_ * 32; i += 128) {
        int c = i >> 10;
        int f = (i >> 5) & 31;
        int k = i & 31;
        s_cw[c][f][k] = (k < KS_) ? cw[(f * 2 + c) * KS_ + k] : 0.f;
    }
    // W_loc [128 a][32 f] -> smem as float4
    for (int i = tid; i < ATT_ * 8; i += 128)
        reinterpret_cast<float4*>(s_wl)[i] = reinterpret_cast<const float4*>(Wl)[i];
    s_pq[tid] = g_pq[b * ATT_ + tid];
    s_v[tid] = vw[tid];
    __syncthreads();

    // ---- conv: loc[0..31] in registers, one channel at a time ----
    float loc[NF_];
#pragma unroll
    for (int i = 0; i < NF_; i++) loc[i] = 0.f;
#pragma unroll
    for (int c = 0; c < 2; c++) {
        float xr[32];
#pragma unroll
        for (int i = 0; i < 32; i++) xr[i] = s_cat[c][tid + i];
#pragma unroll
        for (int j = 0; j < NF_; j++) {
            float a = 0.f;
#pragma unroll
            for (int kk = 0; kk < 8; kk++) {
                float4 w = *reinterpret_cast<const float4*>(&s_cw[c][j][4 * kk]);
                a += w.x * xr[4 * kk] + w.y * xr[4 * kk + 1] +
                     w.z * xr[4 * kk + 2] + w.w * xr[4 * kk + 3];
            }
            loc[j] += a;
        }
    }

    // ---- energies: e[t] = sum_a v[a] * tanh(pq[a] + pm[t,a] + Wl[a,:].loc) ----
    float e = 0.f;
#pragma unroll
    for (int chv = 0; chv < 4; chv++) {
        // stage pm tile [128 t][32 a] into padded smem.
        // NOTE: stride 33 floats => odd-t rows are NOT 16B-aligned, so the
        // store side MUST be scalar (STS.128 here traps: misaligned address).
        // Scalar store banks: (33t+4a4+k)%32 = (t+4a4+k)%32 -> conflict-free.
        __syncthreads();
#pragma unroll
        for (int r = 0; r < 8; r++) {
            int i = r * 128 + tid;          // 0..1023 float4s
            int t = i >> 3, a4 = i & 7;
            float4 v4 = *reinterpret_cast<const float4*>(
                pm + ((size_t)(b * T_) + t0 + t) * ATT_ + chv * 32 + a4 * 4);
            float* dst = &s_pm[t * 33 + a4 * 4];
            dst[0] = v4.x; dst[1] = v4.y; dst[2] = v4.z; dst[3] = v4.w;
        }
        __syncthreads();
#pragma unroll 4
        for (int aa = 0; aa < 32; aa++) {
            int a = chv * 32 + aa;
            float z = s_pq[a] + s_pm[tid * 33 + aa];
#pragma unroll
            for (int j = 0; j < 8; j++) {
                float4 w = s_wl[a][j];
                z += w.x * loc[4 * j] + w.y * loc[4 * j + 1] +
                     w.z * loc[4 * j + 2] + w.w * loc[4 * j + 3];
            }
            float th;
            asm("tanh.approx.f32 %0, %1;" : "=f"(th) : "f"(z));
            e += s_v[a] * th;
        }
    }
    const int gt = b * T_ + t0 + tid;
    if (mask[gt] != 0) e = -CUDART_INF_F;
    g_energy[gt] = e;
}

// ---------------------------------------------------------------------------
// K3a: softmax over T per b. 64 blocks x 256 threads; 8 energies per thread
// held in registers across passes. Writes normalized probs to g_prob AND the
// attention-weights output slice.
// ---------------------------------------------------------------------------
__global__ __launch_bounds__(256) void k_softmax(float* __restrict__ out) {
    const int b = blockIdx.x;
    const int tid = threadIdx.x;
    __shared__ float s_red[8];

    float4 e0 = reinterpret_cast<const float4*>(g_energy + b * T_)[tid * 2];
    float4 e1 = reinterpret_cast<const float4*>(g_energy + b * T_)[tid * 2 + 1];

    float lmax = fmaxf(fmaxf(fmaxf(e0.x, e0.y), fmaxf(e0.z, e0.w)),
                       fmaxf(fmaxf(e1.x, e1.y), fmaxf(e1.z, e1.w)));
#pragma unroll
    for (int off = 16; off; off >>= 1)
        lmax = fmaxf(lmax, __shfl_xor_sync(0xffffffffu, lmax, off));
    if ((tid & 31) == 0) s_red[tid >> 5] = lmax;
    __syncthreads();
    float bmax = s_red[0];
#pragma unroll
    for (int i = 1; i < 8; i++) bmax = fmaxf(bmax, s_red[i]);
    __syncthreads();

    float4 p0 = make_float4(__expf(e0.x - bmax), __expf(e0.y - bmax),
                            __expf(e0.z - bmax), __expf(e0.w - bmax));
    float4 p1 = make_float4(__expf(e1.x - bmax), __expf(e1.y - bmax),
                            __expf(e1.z - bmax), __expf(e1.w - bmax));
    float lsum = (p0.x + p0.y) + (p0.z + p0.w) + (p1.x + p1.y) + (p1.z + p1.w);
#pragma unroll
    for (int off = 16; off; off >>= 1)
        lsum += __shfl_xor_sync(0xffffffffu, lsum, off);
    if ((tid & 31) == 0) s_red[tid >> 5] = lsum;
    __syncthreads();
    float bsum = 0.f;
#pragma unroll
    for (int i = 0; i < 8; i++) bsum += s_red[i];
    const float inv = 1.f / bsum;

    p0.x *= inv; p0.y *= inv; p0.z *= inv; p0.w *= inv;
    p1.x *= inv; p1.y *= inv; p1.z *= inv; p1.w *= inv;
    reinterpret_cast<float4*>(g_prob + b * T_)[tid * 2] = p0;
    reinterpret_cast<float4*>(g_prob + b * T_)[tid * 2 + 1] = p1;
    float* ow = out + B_ * EMB_ + b * T_;
    reinterpret_cast<float4*>(ow)[tid * 2] = p0;
    reinterpret_cast<float4*>(ow)[tid * 2 + 1] = p1;
}

// ---------------------------------------------------------------------------
// K3b: context matvec. grid (4, B), 512 threads = 8 t-phases x 64 d (float2).
// Explicit 8-deep load batching for DRAM MLP.
// ---------------------------------------------------------------------------
__global__ __launch_bounds__(512) void k_ctx(const float* __restrict__ mem,
                                             float* __restrict__ out) {
    const int b = blockIdx.y;
    const int dc = blockIdx.x;      // 0..3 -> 128 dims each
    const int tid = threadIdx.x;

    __shared__ float s_p[T_];
    __shared__ float2 s_acc[512];

    reinterpret_cast<float4*>(s_p)[tid] =
        reinterpret_cast<const float4*>(g_prob + b * T_)[tid];
    __syncthreads();

    const int ph = tid >> 6;        // 0..7
    const float2* mp = reinterpret_cast<const float2*>(
        mem + (size_t)b * T_ * EMB_ + dc * 128) + (tid & 63);
    float2 acc = make_float2(0.f, 0.f);
    for (int tb = ph; tb < T_; tb += 64) {
        float2 r[8];
#pragma unroll
        for (int u = 0; u < 8; u++) r[u] = mp[(size_t)(tb + u * 8) * 256];
#pragma unroll
        for (int u = 0; u < 8; u++) {
            float p = s_p[tb + u * 8];
            acc.x += p * r[u].x;
            acc.y += p * r[u].y;
        }
    }
    s_acc[tid] = acc;
    __syncthreads();
    if (tid < 64) {
        float2 tot = make_float2(0.f, 0.f);
#pragma unroll
        for (int k = 0; k < 8; k++) {
            float2 v = s_acc[k * 64 + tid];
            tot.x += v.x;
            tot.y += v.y;
        }
        reinterpret_cast<float2*>(out + b * EMB_ + dc * 128)[tid] = tot;
    }
}

// ---------------------------------------------------------------------------
extern "C" void kernel_launch(void* const* d_in, const int* in_sizes, int n_in,
                              void* d_out, int out_size) {
    const float* query = (const float*)d_in[0];
    const float* pm    = (const float*)d_in[1];
    const float* cat   = (const float*)d_in[2];
    const int*   mask  = (const int*)d_in[3];
    const float* mem   = (const float*)d_in[4];
    const float* Wq    = (const float*)d_in[5];
    const float* cw    = (const float*)d_in[6];
    const float* Wl    = (const float*)d_in[7];
    const float* vw    = (const float*)d_in[8];
    float* out = (float*)d_out;

    k_query<<<512, 256>>>(query, Wq);
    dim3 g2(T_ / TILE_, B_);
    k_energy<<<g2, 128>>>(pm, cat, mask, cw, Wl, vw);
    k_softmax<<<B_, 256>>>(out);
    dim3 g3(4, B_);
    k_ctx<<<g3, 512>>>(mem, out);
}